// round 1
// baseline (speedup 1.0000x reference)
#include <cuda_runtime.h>
#include <cuda_bf16.h>
#include <cstdint>

// Problem constants
#define BB 4
#define N1 8192
#define N2 2048
#define INP 512
#define OUTP 256
#define M1 (BB * N1)   // 32768
#define M2 (BB * N2)   // 8192

// Device scratch (allocation-free rule: __device__ globals)
__device__ float g_y1[M1 * OUTP];     // x1@W1+b1  (32 MB)
__device__ float g_y2[M2 * OUTP];     // x2@W2+b2  (8 MB)
__device__ float g_stats1[2 * OUTP];  // sum, sumsq
__device__ float g_stats2[2 * OUTP];
__device__ float g_ab1[2 * OUTP];     // scale, shift
__device__ float g_ab2[2 * OUTP];
__device__ int   g_idx[BB * N1 * 3];  // global row index into y2
__device__ float g_w[BB * N1 * 3];

// ---------------------------------------------------------------------------
__global__ void zero_stats_kernel() {
    int t = threadIdx.x;
    if (t < 2 * OUTP) { g_stats1[t] = 0.f; g_stats2[t] = 0.f; }
}

// ---------------------------------------------------------------------------
// Tiled fp32 GEMM: C[M,256] = A[M,K] @ W[K,256] + bias
// BM=128, BN=64, BK=16, 256 threads, each thread computes 8x4.
#define BM 128
#define BN 64
#define BK 16
#define TM 8
#define TN 4

template<int K>
__global__ __launch_bounds__(256) void gemm_bias_kernel(
    const float* __restrict__ A, const float* __restrict__ W,
    const float* __restrict__ bias, float* __restrict__ C)
{
    __shared__ float As[BK][BM];   // transposed A tile
    __shared__ float Bs[BK][BN];

    const int tid = threadIdx.x;
    const int tx = tid & 15;       // 16 col groups of 4
    const int ty = tid >> 4;       // 16 row groups of 8
    const int block_row = blockIdx.y * BM;
    const int block_col = blockIdx.x * BN;

    float acc[TM][TN];
    #pragma unroll
    for (int i = 0; i < TM; i++)
        #pragma unroll
        for (int j = 0; j < TN; j++) acc[i][j] = 0.f;

    for (int k0 = 0; k0 < K; k0 += BK) {
        // Load A tile: 128 rows x 16 k = 512 float4, 2 per thread
        #pragma unroll
        for (int l = 0; l < 2; l++) {
            int i  = tid + l * 256;        // 0..511
            int r  = i >> 2;               // 0..127
            int c4 = (i & 3) * 4;          // 0,4,8,12
            float4 v = *(const float4*)(A + (size_t)(block_row + r) * K + k0 + c4);
            As[c4 + 0][r] = v.x;
            As[c4 + 1][r] = v.y;
            As[c4 + 2][r] = v.z;
            As[c4 + 3][r] = v.w;
        }
        // Load B tile: 16 k x 64 cols = 256 float4, 1 per thread
        {
            int r  = tid >> 4;             // 0..15
            int c4 = (tid & 15) * 4;       // 0..60
            float4 v = *(const float4*)(W + (size_t)(k0 + r) * OUTP + block_col + c4);
            *(float4*)&Bs[r][c4] = v;
        }
        __syncthreads();

        #pragma unroll
        for (int kk = 0; kk < BK; kk++) {
            float a[TM], b[TN];
            #pragma unroll
            for (int i = 0; i < TM; i++) a[i] = As[kk][ty * TM + i];
            #pragma unroll
            for (int j = 0; j < TN; j++) b[j] = Bs[kk][tx * TN + j];
            #pragma unroll
            for (int i = 0; i < TM; i++)
                #pragma unroll
                for (int j = 0; j < TN; j++)
                    acc[i][j] = fmaf(a[i], b[j], acc[i][j]);
        }
        __syncthreads();
    }

    const int cbase = block_col + tx * TN;
    float4 bv = *(const float4*)(bias + cbase);
    #pragma unroll
    for (int i = 0; i < TM; i++) {
        int r = block_row + ty * TM + i;
        float4 v;
        v.x = acc[i][0] + bv.x;
        v.y = acc[i][1] + bv.y;
        v.z = acc[i][2] + bv.z;
        v.w = acc[i][3] + bv.w;
        *(float4*)(C + (size_t)r * OUTP + cbase) = v;
    }
}

// ---------------------------------------------------------------------------
// Per-channel sum / sumsq. Thread c accumulates channel c over a stride of rows.
__global__ __launch_bounds__(256) void stats_kernel(
    const float* __restrict__ y, int rows, float* __restrict__ stats)
{
    int c = threadIdx.x;
    float s = 0.f, q = 0.f;
    for (int r = blockIdx.x; r < rows; r += gridDim.x) {
        float v = y[(size_t)r * OUTP + c];
        s += v;
        q = fmaf(v, v, q);
    }
    atomicAdd(&stats[c], s);
    atomicAdd(&stats[OUTP + c], q);
}

__global__ void finalize_kernel(const float* __restrict__ stats,
                                const float* __restrict__ gamma,
                                const float* __restrict__ beta,
                                float inv_count, float* __restrict__ ab)
{
    int c = threadIdx.x;
    float mean = stats[c] * inv_count;
    float var  = stats[OUTP + c] * inv_count - mean * mean;
    float scale = gamma[c] * rsqrtf(var + 1e-5f);
    ab[c]        = scale;
    ab[OUTP + c] = beta[c] - mean * scale;
}

// ---------------------------------------------------------------------------
// 3-NN: block = 256 p1 points of one batch; p2 of that batch cached in smem.
// Distance uses the reference's expanded form: |p1|^2 + |p2|^2 - 2*dot.
__global__ __launch_bounds__(256) void knn_kernel(
    const float* __restrict__ p1, const float* __restrict__ p2)
{
    __shared__ float sx[N2], sy[N2], sz[N2], ss[N2];
    const int b     = blockIdx.x >> 5;   // N1/256 = 32 chunks per batch
    const int chunk = blockIdx.x & 31;

    const float* P2 = p2 + (size_t)b * N2 * 3;
    for (int i = threadIdx.x; i < N2; i += 256) {
        float x = P2[i * 3 + 0], y = P2[i * 3 + 1], z = P2[i * 3 + 2];
        sx[i] = x; sy[i] = y; sz[i] = z;
        ss[i] = fmaf(x, x, fmaf(y, y, z * z));
    }
    __syncthreads();

    const int n = chunk * 256 + threadIdx.x;
    const float* P1 = p1 + ((size_t)b * N1 + n) * 3;
    const float px = P1[0], py = P1[1], pz = P1[2];
    const float s1 = fmaf(px, px, fmaf(py, py, pz * pz));

    float d0 = 1e30f, d1 = 1e30f, d2 = 1e30f;
    int   i0 = 0,     i1 = 0,     i2 = 0;

    #pragma unroll 4
    for (int j = 0; j < N2; j++) {
        float dot = fmaf(px, sx[j], fmaf(py, sy[j], pz * sz[j]));
        float d = (s1 + ss[j]) - 2.f * dot;
        if (d < d2) {
            if (d < d1) {
                d2 = d1; i2 = i1;
                if (d < d0) { d1 = d0; i1 = i0; d0 = d; i0 = j; }
                else        { d1 = d;  i1 = j; }
            } else { d2 = d; i2 = j; }
        }
    }

    float r0 = 1.f / (d0 + 1e-8f);
    float r1 = 1.f / (d1 + 1e-8f);
    float r2 = 1.f / (d2 + 1e-8f);
    float rs = 1.f / (r0 + r1 + r2);

    size_t o = ((size_t)b * N1 + n) * 3;
    g_idx[o + 0] = b * N2 + i0;
    g_idx[o + 1] = b * N2 + i1;
    g_idx[o + 2] = b * N2 + i2;
    g_w[o + 0] = r0 * rs;
    g_w[o + 1] = r1 * rs;
    g_w[o + 2] = r2 * rs;
}

// ---------------------------------------------------------------------------
// out[r,c] = relu(y1*a1+s1) + sum_k w_k * relu(y2[idx_k]*a2+s2)
__global__ __launch_bounds__(256) void out_kernel(float* __restrict__ out)
{
    const int r = blockIdx.x;      // 0..32767
    const int c = threadIdx.x;     // 0..255

    const float a1 = g_ab1[c], s1 = g_ab1[OUTP + c];
    const float a2 = g_ab2[c], s2 = g_ab2[OUTP + c];

    const size_t o3 = (size_t)r * 3;
    const int   j0 = g_idx[o3 + 0], j1 = g_idx[o3 + 1], j2 = g_idx[o3 + 2];
    const float w0 = g_w[o3 + 0],   w1 = g_w[o3 + 1],   w2 = g_w[o3 + 2];

    float v1 = fmaxf(fmaf(g_y1[(size_t)r * OUTP + c], a1, s1), 0.f);
    float h0 = fmaxf(fmaf(g_y2[(size_t)j0 * OUTP + c], a2, s2), 0.f);
    float h1 = fmaxf(fmaf(g_y2[(size_t)j1 * OUTP + c], a2, s2), 0.f);
    float h2 = fmaxf(fmaf(g_y2[(size_t)j2 * OUTP + c], a2, s2), 0.f);

    out[(size_t)r * OUTP + c] = v1 + fmaf(w0, h0, fmaf(w1, h1, w2 * h2));
}

// ---------------------------------------------------------------------------
extern "C" void kernel_launch(void* const* d_in, const int* in_sizes, int n_in,
                              void* d_out, int out_size)
{
    const float* p1     = (const float*)d_in[0];
    const float* x1     = (const float*)d_in[1];
    const float* p2     = (const float*)d_in[2];
    const float* x2     = (const float*)d_in[3];
    const float* W1     = (const float*)d_in[4];
    const float* b1     = (const float*)d_in[5];
    const float* gamma1 = (const float*)d_in[6];
    const float* beta1  = (const float*)d_in[7];
    const float* W2     = (const float*)d_in[8];
    const float* b2     = (const float*)d_in[9];
    const float* gamma2 = (const float*)d_in[10];
    const float* beta2  = (const float*)d_in[11];
    float* out = (float*)d_out;

    float *y1, *y2, *st1, *st2, *ab1, *ab2;
    cudaGetSymbolAddress((void**)&y1,  g_y1);
    cudaGetSymbolAddress((void**)&y2,  g_y2);
    cudaGetSymbolAddress((void**)&st1, g_stats1);
    cudaGetSymbolAddress((void**)&st2, g_stats2);
    cudaGetSymbolAddress((void**)&ab1, g_ab1);
    cudaGetSymbolAddress((void**)&ab2, g_ab2);

    zero_stats_kernel<<<1, 512>>>();

    // GEMM2: [8192,512] x [512,256]
    gemm_bias_kernel<INP><<<dim3(OUTP / BN, M2 / BM), 256>>>(x2, W2, b2, y2);
    // GEMM1: [32768,256] x [256,256]
    gemm_bias_kernel<OUTP><<<dim3(OUTP / BN, M1 / BM), 256>>>(x1, W1, b1, y1);

    stats_kernel<<<256, 256>>>(y2, M2, st2);
    stats_kernel<<<256, 256>>>(y1, M1, st1);

    finalize_kernel<<<1, 256>>>(st2, gamma2, beta2, 1.f / (float)M2, ab2);
    finalize_kernel<<<1, 256>>>(st1, gamma1, beta1, 1.f / (float)M1, ab1);

    knn_kernel<<<BB * (N1 / 256), 256>>>(p1, p2);

    out_kernel<<<M1, 256>>>(out);
}

// round 3
// speedup vs baseline: 1.5471x; 1.5471x over previous
#include <cuda_runtime.h>
#include <cuda_bf16.h>
#include <cstdint>

// Problem constants
#define BB 4
#define N1 8192
#define N2 2048
#define INP 512
#define OUTP 256
#define M1 (BB * N1)   // 32768
#define M2 (BB * N2)   // 8192

// Device scratch (allocation-free rule)
__device__ float g_y1[M1 * OUTP];     // x1@W1+b1  (32 MB)
__device__ float g_y2[M2 * OUTP];     // x2@W2+b2  (8 MB)
__device__ float g_Wt1[OUTP * OUTP];  // W1^T  [N,K]
__device__ float g_Wt2[OUTP * INP];   // W2^T  [N,K]
__device__ float g_stats1[2 * OUTP];
__device__ float g_stats2[2 * OUTP];
__device__ float g_ab1[2 * OUTP];
__device__ float g_ab2[2 * OUTP];
__device__ int   g_idx[BB * N1 * 3];
__device__ float g_w[BB * N1 * 3];

// ---------------------------------------------------------------------------
__device__ __forceinline__ uint32_t smem_u32(const void* p) {
    uint32_t a;
    asm("{ .reg .u64 t; cvta.to.shared.u64 t, %1; cvt.u32.u64 %0, t; }"
        : "=r"(a) : "l"(p));
    return a;
}

__device__ __forceinline__ void ldmx4(uint32_t addr, uint32_t* r) {
    asm volatile("ldmatrix.sync.aligned.m8n8.x4.shared.b16 {%0,%1,%2,%3}, [%4];"
                 : "=r"(r[0]), "=r"(r[1]), "=r"(r[2]), "=r"(r[3]) : "r"(addr));
}

__device__ __forceinline__ void mma16816(float* c, const uint32_t* a,
                                         const uint32_t* b) {
    asm volatile(
        "mma.sync.aligned.m16n8k16.row.col.f32.bf16.bf16.f32 "
        "{%0,%1,%2,%3}, {%4,%5,%6,%7}, {%8,%9}, {%0,%1,%2,%3};"
        : "+f"(c[0]), "+f"(c[1]), "+f"(c[2]), "+f"(c[3])
        : "r"(a[0]), "r"(a[1]), "r"(a[2]), "r"(a[3]), "r"(b[0]), "r"(b[1]));
}

// ---------------------------------------------------------------------------
__global__ void zero_stats_kernel() {
    int t = threadIdx.x;
    if (t < 2 * OUTP) { g_stats1[t] = 0.f; g_stats2[t] = 0.f; }
}

// Tiled transpose: dst[C][R] = src[R][C]^T. block (32,8), grid (C/32, R/32)
__global__ __launch_bounds__(256) void transpose_kernel(
    const float* __restrict__ src, float* __restrict__ dst, int R, int C)
{
    __shared__ float t[32][33];
    int bx = blockIdx.x * 32, by = blockIdx.y * 32;
    int x = bx + threadIdx.x;
    #pragma unroll
    for (int i = 0; i < 32; i += 8)
        t[threadIdx.y + i][threadIdx.x] = src[(size_t)(by + threadIdx.y + i) * C + x];
    __syncthreads();
    int x2 = by + threadIdx.x;
    #pragma unroll
    for (int i = 0; i < 32; i += 8)
        dst[(size_t)(bx + threadIdx.y + i) * R + x2] = t[threadIdx.x][threadIdx.y + i];
}

// ---------------------------------------------------------------------------
// Split-bf16 HMMA GEMM: C[M,256] = A[M,K] @ Wt[256,K]^T + bias
// CTA tile 128x128, BK=32, 8 warps (warp tile 64x32).
// A,B split into bf16 hi/lo in smem; 3-term MMA (hh + hl + lh), fp32 acc.
#define ROWE 40            // smem row stride in bf16 elements (80 bytes)
#define ROWB 80

template<int K>
__global__ __launch_bounds__(256) void gemm_hmma_kernel(
    const float* __restrict__ A, const float* __restrict__ Wt,
    const float* __restrict__ bias, float* __restrict__ C)
{
    __shared__ __nv_bfloat16 sAhi[128 * ROWE];
    __shared__ __nv_bfloat16 sAlo[128 * ROWE];
    __shared__ __nv_bfloat16 sBhi[128 * ROWE];
    __shared__ __nv_bfloat16 sBlo[128 * ROWE];

    const int tid = threadIdx.x;
    const int wid = tid >> 5;
    const int lane = tid & 31;
    const int gid = lane >> 2;   // mma group
    const int tig = lane & 3;

    const int rowBase = blockIdx.y * 128;
    const int colBase = blockIdx.x * 128;
    const int m0 = (wid & 1) * 64;
    const int n0 = (wid >> 1) * 32;

    const uint32_t uAhi = smem_u32(sAhi), uAlo = smem_u32(sAlo);
    const uint32_t uBhi = smem_u32(sBhi), uBlo = smem_u32(sBlo);

    // ldmatrix per-lane address components
    const int q = lane >> 3, ri = lane & 7;
    const uint32_t aOff = (uint32_t)(m0 + (q & 1) * 8 + ri) * ROWB + (q >> 1) * 16;
    const uint32_t bOff = (uint32_t)(n0 + (q >> 1) * 8 + ri) * ROWB + (q & 1) * 16;

    // Loader indices: i = tid + l*256; row = i>>3, c4 = (i&7)*4
    const int ldRow = tid >> 3;
    const int ldC4  = (tid & 7) * 4;

    float acc[4][4][4];
    #pragma unroll
    for (int mt = 0; mt < 4; mt++)
        #pragma unroll
        for (int nt = 0; nt < 4; nt++)
            #pragma unroll
            for (int e = 0; e < 4; e++) acc[mt][nt][e] = 0.f;

    for (int k0 = 0; k0 < K; k0 += 32) {
        // ---- load + split-convert A tile (128 x 32 fp32) ----
        #pragma unroll
        for (int l = 0; l < 4; l++) {
            int r = ldRow + l * 32;
            float4 v = *(const float4*)(A + (size_t)(rowBase + r) * K + k0 + ldC4);
            __nv_bfloat16 h0 = __float2bfloat16_rn(v.x);
            __nv_bfloat16 h1 = __float2bfloat16_rn(v.y);
            __nv_bfloat16 h2 = __float2bfloat16_rn(v.z);
            __nv_bfloat16 h3 = __float2bfloat16_rn(v.w);
            __nv_bfloat16 l0 = __float2bfloat16_rn(v.x - __bfloat162float(h0));
            __nv_bfloat16 l1 = __float2bfloat16_rn(v.y - __bfloat162float(h1));
            __nv_bfloat16 l2 = __float2bfloat16_rn(v.z - __bfloat162float(h2));
            __nv_bfloat16 l3 = __float2bfloat16_rn(v.w - __bfloat162float(h3));
            __nv_bfloat162 hA(h0, h1), hB(h2, h3), lA(l0, l1), lB(l2, l3);
            int o = r * ROWE + ldC4;
            *(uint2*)&sAhi[o] = make_uint2(*(uint32_t*)&hA, *(uint32_t*)&hB);
            *(uint2*)&sAlo[o] = make_uint2(*(uint32_t*)&lA, *(uint32_t*)&lB);
        }
        // ---- load + split-convert B tile (128 x 32 fp32 of Wt) ----
        #pragma unroll
        for (int l = 0; l < 4; l++) {
            int r = ldRow + l * 32;
            float4 v = *(const float4*)(Wt + (size_t)(colBase + r) * K + k0 + ldC4);
            __nv_bfloat16 h0 = __float2bfloat16_rn(v.x);
            __nv_bfloat16 h1 = __float2bfloat16_rn(v.y);
            __nv_bfloat16 h2 = __float2bfloat16_rn(v.z);
            __nv_bfloat16 h3 = __float2bfloat16_rn(v.w);
            __nv_bfloat16 l0 = __float2bfloat16_rn(v.x - __bfloat162float(h0));
            __nv_bfloat16 l1 = __float2bfloat16_rn(v.y - __bfloat162float(h1));
            __nv_bfloat16 l2 = __float2bfloat16_rn(v.z - __bfloat162float(h2));
            __nv_bfloat16 l3 = __float2bfloat16_rn(v.w - __bfloat162float(h3));
            __nv_bfloat162 hA(h0, h1), hB(h2, h3), lA(l0, l1), lB(l2, l3);
            int o = r * ROWE + ldC4;
            *(uint2*)&sBhi[o] = make_uint2(*(uint32_t*)&hA, *(uint32_t*)&hB);
            *(uint2*)&sBlo[o] = make_uint2(*(uint32_t*)&lA, *(uint32_t*)&lB);
        }
        __syncthreads();

        // ---- MMA: 2 k16 steps, 4 m-tiles x 4 n-tiles, 3 split terms ----
        #pragma unroll
        for (int kk = 0; kk < 2; kk++) {
            uint32_t bh[4][2], bl[4][2];
            #pragma unroll
            for (int p = 0; p < 2; p++) {
                uint32_t r4[4];
                ldmx4(uBhi + bOff + p * 16 * ROWB + kk * 32, r4);
                bh[2 * p][0] = r4[0]; bh[2 * p][1] = r4[1];
                bh[2 * p + 1][0] = r4[2]; bh[2 * p + 1][1] = r4[3];
                ldmx4(uBlo + bOff + p * 16 * ROWB + kk * 32, r4);
                bl[2 * p][0] = r4[0]; bl[2 * p][1] = r4[1];
                bl[2 * p + 1][0] = r4[2]; bl[2 * p + 1][1] = r4[3];
            }
            #pragma unroll
            for (int mt = 0; mt < 4; mt++) {
                uint32_t ah[4], al[4];
                ldmx4(uAhi + aOff + mt * 16 * ROWB + kk * 32, ah);
                ldmx4(uAlo + aOff + mt * 16 * ROWB + kk * 32, al);
                #pragma unroll
                for (int nt = 0; nt < 4; nt++) {
                    mma16816(acc[mt][nt], ah, bh[nt]);
                    mma16816(acc[mt][nt], ah, bl[nt]);
                    mma16816(acc[mt][nt], al, bh[nt]);
                }
            }
        }
        __syncthreads();
    }

    // ---- epilogue: acc + bias -> C ----
    #pragma unroll
    for (int nt = 0; nt < 4; nt++) {
        const int cg = colBase + n0 + nt * 8 + tig * 2;
        float2 bv = *(const float2*)(bias + cg);
        #pragma unroll
        for (int mt = 0; mt < 4; mt++) {
            int rg0 = rowBase + m0 + mt * 16 + gid;
            float2 v0 = make_float2(acc[mt][nt][0] + bv.x, acc[mt][nt][1] + bv.y);
            float2 v1 = make_float2(acc[mt][nt][2] + bv.x, acc[mt][nt][3] + bv.y);
            *(float2*)(C + (size_t)rg0 * OUTP + cg) = v0;
            *(float2*)(C + (size_t)(rg0 + 8) * OUTP + cg) = v1;
        }
    }
}

// ---------------------------------------------------------------------------
__global__ __launch_bounds__(256) void stats_kernel(
    const float* __restrict__ y, int rows, float* __restrict__ stats)
{
    int c = threadIdx.x;
    float s = 0.f, q = 0.f;
    for (int r = blockIdx.x; r < rows; r += gridDim.x) {
        float v = y[(size_t)r * OUTP + c];
        s += v;
        q = fmaf(v, v, q);
    }
    atomicAdd(&stats[c], s);
    atomicAdd(&stats[OUTP + c], q);
}

__global__ void finalize_kernel(const float* __restrict__ stats,
                                const float* __restrict__ gamma,
                                const float* __restrict__ beta,
                                float inv_count, float* __restrict__ ab)
{
    int c = threadIdx.x;
    float mean = stats[c] * inv_count;
    float var  = stats[OUTP + c] * inv_count - mean * mean;
    float scale = gamma[c] * rsqrtf(var + 1e-5f);
    ab[c]        = scale;
    ab[OUTP + c] = beta[c] - mean * scale;
}

// ---------------------------------------------------------------------------
__global__ __launch_bounds__(256) void knn_kernel(
    const float* __restrict__ p1, const float* __restrict__ p2)
{
    __shared__ float4 sp[N2];
    const int b     = blockIdx.x >> 5;
    const int chunk = blockIdx.x & 31;

    const float* P2 = p2 + (size_t)b * N2 * 3;
    for (int i = threadIdx.x; i < N2; i += 256) {
        float x = P2[i * 3 + 0], y = P2[i * 3 + 1], z = P2[i * 3 + 2];
        sp[i] = make_float4(x, y, z, fmaf(x, x, fmaf(y, y, z * z)));
    }
    __syncthreads();

    const int n = chunk * 256 + threadIdx.x;
    const float* P1 = p1 + ((size_t)b * N1 + n) * 3;
    const float px = P1[0], py = P1[1], pz = P1[2];
    const float s1 = fmaf(px, px, fmaf(py, py, pz * pz));

    float d0 = 1e30f, d1 = 1e30f, d2 = 1e30f;
    int   i0 = 0,     i1 = 0,     i2 = 0;

    #pragma unroll 4
    for (int j = 0; j < N2; j++) {
        float4 qq = sp[j];
        float dot = fmaf(px, qq.x, fmaf(py, qq.y, pz * qq.z));
        float d = (s1 + qq.w) - 2.f * dot;
        if (d < d2) {
            if (d < d1) {
                d2 = d1; i2 = i1;
                if (d < d0) { d1 = d0; i1 = i0; d0 = d; i0 = j; }
                else        { d1 = d;  i1 = j; }
            } else { d2 = d; i2 = j; }
        }
    }

    float r0 = 1.f / (d0 + 1e-8f);
    float r1 = 1.f / (d1 + 1e-8f);
    float r2 = 1.f / (d2 + 1e-8f);
    float rs = 1.f / (r0 + r1 + r2);

    size_t o = ((size_t)b * N1 + n) * 3;
    g_idx[o + 0] = b * N2 + i0;
    g_idx[o + 1] = b * N2 + i1;
    g_idx[o + 2] = b * N2 + i2;
    g_w[o + 0] = r0 * rs;
    g_w[o + 1] = r1 * rs;
    g_w[o + 2] = r2 * rs;
}

// ---------------------------------------------------------------------------
__global__ __launch_bounds__(256) void out_kernel(float* __restrict__ out)
{
    const int r = blockIdx.x;
    const int c = threadIdx.x;

    const float a1 = g_ab1[c], s1 = g_ab1[OUTP + c];
    const float a2 = g_ab2[c], s2 = g_ab2[OUTP + c];

    const size_t o3 = (size_t)r * 3;
    const int   j0 = g_idx[o3 + 0], j1 = g_idx[o3 + 1], j2 = g_idx[o3 + 2];
    const float w0 = g_w[o3 + 0],   w1 = g_w[o3 + 1],   w2 = g_w[o3 + 2];

    float v1 = fmaxf(fmaf(g_y1[(size_t)r * OUTP + c], a1, s1), 0.f);
    float h0 = fmaxf(fmaf(g_y2[(size_t)j0 * OUTP + c], a2, s2), 0.f);
    float h1 = fmaxf(fmaf(g_y2[(size_t)j1 * OUTP + c], a2, s2), 0.f);
    float h2 = fmaxf(fmaf(g_y2[(size_t)j2 * OUTP + c], a2, s2), 0.f);

    out[(size_t)r * OUTP + c] = v1 + fmaf(w0, h0, fmaf(w1, h1, w2 * h2));
}

// ---------------------------------------------------------------------------
extern "C" void kernel_launch(void* const* d_in, const int* in_sizes, int n_in,
                              void* d_out, int out_size)
{
    const float* p1     = (const float*)d_in[0];
    const float* x1     = (const float*)d_in[1];
    const float* p2     = (const float*)d_in[2];
    const float* x2     = (const float*)d_in[3];
    const float* W1     = (const float*)d_in[4];
    const float* b1     = (const float*)d_in[5];
    const float* gamma1 = (const float*)d_in[6];
    const float* beta1  = (const float*)d_in[7];
    const float* W2     = (const float*)d_in[8];
    const float* b2     = (const float*)d_in[9];
    const float* gamma2 = (const float*)d_in[10];
    const float* beta2  = (const float*)d_in[11];
    float* out = (float*)d_out;

    float *y1, *y2, *st1, *st2, *ab1, *ab2, *wt1, *wt2;
    cudaGetSymbolAddress((void**)&y1,  g_y1);
    cudaGetSymbolAddress((void**)&y2,  g_y2);
    cudaGetSymbolAddress((void**)&st1, g_stats1);
    cudaGetSymbolAddress((void**)&st2, g_stats2);
    cudaGetSymbolAddress((void**)&ab1, g_ab1);
    cudaGetSymbolAddress((void**)&ab2, g_ab2);
    cudaGetSymbolAddress((void**)&wt1, g_Wt1);
    cudaGetSymbolAddress((void**)&wt2, g_Wt2);

    zero_stats_kernel<<<1, 512>>>();

    // Transpose weights into [N,K]
    transpose_kernel<<<dim3(OUTP / 32, INP / 32), dim3(32, 8)>>>(W2, wt2, INP, OUTP);
    transpose_kernel<<<dim3(OUTP / 32, OUTP / 32), dim3(32, 8)>>>(W1, wt1, OUTP, OUTP);

    // Split-bf16 HMMA GEMMs
    gemm_hmma_kernel<INP><<<dim3(2, M2 / 128), 256>>>(x2, wt2, b2, y2);
    gemm_hmma_kernel<OUTP><<<dim3(2, M1 / 128), 256>>>(x1, wt1, b1, y1);

    stats_kernel<<<512, 256>>>(y2, M2, st2);
    stats_kernel<<<2048, 256>>>(y1, M1, st1);

    finalize_kernel<<<1, 256>>>(st2, gamma2, beta2, 1.f / (float)M2, ab2);
    finalize_kernel<<<1, 256>>>(st1, gamma1, beta1, 1.f / (float)M1, ab1);

    knn_kernel<<<BB * (N1 / 256), 256>>>(p1, p2);

    out_kernel<<<M1, 256>>>(out);
}